// round 5
// baseline (speedup 1.0000x reference)
#include <cuda_runtime.h>
#include <math.h>

#define T_      3
#define RESO    24
#define DIM_    768
#define HEADS_  16
#define DH_     48
#define EMB_    1024
#define MLP_    3072
#define HW      576              // RESO*RESO
#define NTOK    1728             // T_*HW
#define FUSED_N 5376             // 3*DIM_ + MLP_
#define EPS_    1e-5f

// ---------------- scratch (device globals; no runtime allocation) -------------
__device__ float g_mod[T_ * 2 * DIM_];          // [t][1536]  (scale | shift)
__device__ float g_h[NTOK * DIM_];              // modulated LN(x)
__device__ float g_fused[(size_t)NTOK * FUSED_N];
__device__ float g_q[HEADS_ * NTOK * DH_];      // [head][n][dh]
__device__ float g_k[HEADS_ * NTOK * DH_];
__device__ float g_v[HEADS_ * NTOK * DH_];
__device__ float g_xa[NTOK * DIM_];             // attn output, channel = head*48+dh

__device__ __forceinline__ float silu_f(float x) { return x / (1.f + expf(-x)); }

// ---------------- kernel 1: mod = silu(emb) @ w_mod + b_mod (3x1536) ----------
__global__ void k_mod(const float* __restrict__ emb,
                      const float* __restrict__ w_mod,
                      const float* __restrict__ b_mod) {
    __shared__ float se[EMB_];
    int t = blockIdx.y;
    for (int i = threadIdx.x; i < EMB_; i += 256)
        se[i] = silu_f(emb[t * EMB_ + i]);
    __syncthreads();
    int j = blockIdx.x * 256 + threadIdx.x;   // 0..1535
    float acc = b_mod[j];
#pragma unroll 4
    for (int e = 0; e < EMB_; e++)
        acc += se[e] * w_mod[e * (2 * DIM_) + j];
    g_mod[t * (2 * DIM_) + j] = acc;
}

// ---------------- kernel 2: h = LN(x) * (1+scale) + shift ---------------------
__global__ void k_ln(const float* __restrict__ x) {
    int n = blockIdx.x;
    int t = n / HW, hw = n % HW;
    const float* xp = x + (size_t)t * DIM_ * HW + hw;
    int c0 = threadIdx.x, c1 = c0 + 256, c2 = c0 + 512;
    float v0 = xp[(size_t)c0 * HW];
    float v1 = xp[(size_t)c1 * HW];
    float v2 = xp[(size_t)c2 * HW];
    float s  = v0 + v1 + v2;
    float sq = v0 * v0 + v1 * v1 + v2 * v2;
    __shared__ float rs[8], rq[8];
#pragma unroll
    for (int o = 16; o; o >>= 1) {
        s  += __shfl_xor_sync(~0u, s, o);
        sq += __shfl_xor_sync(~0u, sq, o);
    }
    int wid = threadIdx.x >> 5, lid = threadIdx.x & 31;
    if (lid == 0) { rs[wid] = s; rq[wid] = sq; }
    __syncthreads();
    if (threadIdx.x == 0) {
        float ts = 0.f, tq = 0.f;
        for (int i = 0; i < 8; i++) { ts += rs[i]; tq += rq[i]; }
        rs[0] = ts; rq[0] = tq;
    }
    __syncthreads();
    float mean = rs[0] * (1.f / DIM_);
    float var  = rq[0] * (1.f / DIM_) - mean * mean;
    float inv  = rsqrtf(var + EPS_);
    const float* md = g_mod + t * (2 * DIM_);
    float* hp = g_h + (size_t)n * DIM_;
    hp[c0] = (v0 - mean) * inv * (1.f + md[c0]) + md[DIM_ + c0];
    hp[c1] = (v1 - mean) * inv * (1.f + md[c1]) + md[DIM_ + c1];
    hp[c2] = (v2 - mean) * inv * (1.f + md[c2]) + md[DIM_ + c2];
}

// ---------------- kernel 3: fused = h @ W_fused + b_fused ---------------------
// M=1728 K=768 N=5376, BM=64 BN=128 BK=16, 256 thr, 4x8 per thread
__global__ void __launch_bounds__(256) k_gemm1(const float* __restrict__ Wf,
                                               const float* __restrict__ bf) {
    __shared__ float As[16][68];     // [k][m]
    __shared__ float Bs[16][128];    // [k][n]
    int bm = blockIdx.y * 64, bn = blockIdx.x * 128;
    int tid = threadIdx.x;
    int tx = tid & 15, ty = tid >> 4;
    float acc[4][8];
#pragma unroll
    for (int i = 0; i < 4; i++)
#pragma unroll
        for (int j = 0; j < 8; j++) acc[i][j] = 0.f;

    int am = tid >> 2, ak4 = tid & 3;
    for (int k0 = 0; k0 < DIM_; k0 += 16) {
        float4 a = *(const float4*)(g_h + (size_t)(bm + am) * DIM_ + k0 + ak4 * 4);
        As[ak4 * 4 + 0][am] = a.x;
        As[ak4 * 4 + 1][am] = a.y;
        As[ak4 * 4 + 2][am] = a.z;
        As[ak4 * 4 + 3][am] = a.w;
#pragma unroll
        for (int p = 0; p < 2; p++) {
            int idx = tid + p * 256;
            int r = idx >> 5, c4 = idx & 31;
            *(float4*)&Bs[r][c4 * 4] =
                *(const float4*)(Wf + (size_t)(k0 + r) * FUSED_N + bn + c4 * 4);
        }
        __syncthreads();
#pragma unroll
        for (int k = 0; k < 16; k++) {
            float4 av = *(const float4*)&As[k][ty * 4];
            float4 b0 = *(const float4*)&Bs[k][tx * 8];
            float4 b1 = *(const float4*)&Bs[k][tx * 8 + 4];
            float aa[4] = {av.x, av.y, av.z, av.w};
            float bb[8] = {b0.x, b0.y, b0.z, b0.w, b1.x, b1.y, b1.z, b1.w};
#pragma unroll
            for (int i = 0; i < 4; i++)
#pragma unroll
                for (int j = 0; j < 8; j++) acc[i][j] += aa[i] * bb[j];
        }
        __syncthreads();
    }
#pragma unroll
    for (int i = 0; i < 4; i++) {
        int row = bm + ty * 4 + i;
#pragma unroll
        for (int j = 0; j < 8; j++) {
            int col = bn + tx * 8 + j;
            g_fused[(size_t)row * FUSED_N + col] = acc[i][j] + bf[col];
        }
    }
}

// ---------------- kernel 4: qk-norm + RoPE + scatter q/k/v --------------------
__global__ void __launch_bounds__(512) k_qkv(const float* __restrict__ qn_w,
                                             const float* __restrict__ qn_b,
                                             const float* __restrict__ kn_w,
                                             const float* __restrict__ kn_b) {
    int n = blockIdx.x;
    int head = threadIdx.x >> 5;
    int lane = threadIdx.x & 31;
    int t = n / HW, hh = (n % HW) / RESO, ww = n % RESO;
    const float* fp = g_fused + (size_t)n * FUSED_N + head * DH_;
    float2 q2 = make_float2(0.f, 0.f), k2 = q2, v2 = q2;
    if (lane < 24) {
        q2 = *(const float2*)(fp + 2 * lane);
        k2 = *(const float2*)(fp + DIM_ + 2 * lane);
        v2 = *(const float2*)(fp + 2 * DIM_ + 2 * lane);
    }
    float qs = q2.x + q2.y, qq = q2.x * q2.x + q2.y * q2.y;
    float ks = k2.x + k2.y, kq = k2.x * k2.x + k2.y * k2.y;
#pragma unroll
    for (int o = 16; o; o >>= 1) {
        qs += __shfl_xor_sync(~0u, qs, o);
        qq += __shfl_xor_sync(~0u, qq, o);
        ks += __shfl_xor_sync(~0u, ks, o);
        kq += __shfl_xor_sync(~0u, kq, o);
    }
    if (lane < 24) {
        float qm = qs * (1.f / DH_), qv = qq * (1.f / DH_) - qm * qm;
        float km = ks * (1.f / DH_), kv = kq * (1.f / DH_) - km * km;
        float qi = rsqrtf(qv + EPS_), ki = rsqrtf(kv + EPS_);
        int j0 = 2 * lane, j1 = j0 + 1;
        float qn0 = (q2.x - qm) * qi * qn_w[j0] + qn_b[j0];
        float qn1 = (q2.y - qm) * qi * qn_w[j1] + qn_b[j1];
        float kn0 = (k2.x - km) * ki * kn_w[j0] + kn_b[j0];
        float kn1 = (k2.y - km) * ki * kn_w[j1] + kn_b[j1];
        int i = lane;
        int idx;  float pos;
        if (i < 8)       { idx = i;      pos = (float)t;  }
        else if (i < 16) { idx = i - 8;  pos = (float)hh; }
        else             { idx = i - 16; pos = (float)ww; }
        float ang = pos * powf(10000.f, -(float)idx * 0.125f);
        float c = cosf(ang), sn = sinf(ang);
        const float qsc = 0.14433756729740643f;  // 48^-0.5
        size_t base = ((size_t)head * NTOK + n) * DH_;
        *(float2*)(g_q + base + j0) =
            make_float2((qn0 * c - qn1 * sn) * qsc, (qn0 * sn + qn1 * c) * qsc);
        *(float2*)(g_k + base + j0) =
            make_float2(kn0 * c - kn1 * sn, kn0 * sn + kn1 * c);
        *(float2*)(g_v + base + j0) = v2;
    }
}

// ---------------- kernel 5: neighborhood attention (75 nbrs) ------------------
__global__ void __launch_bounds__(512) k_attn() {
    __shared__ float sq[HEADS_][DH_];
    int n = blockIdx.x;
    int head = threadIdx.x >> 5, lane = threadIdx.x & 31;
    int hh = (n % HW) / RESO, ww = n % RESO;
    size_t hb = (size_t)head * NTOK * DH_;
    if (lane < 24)
        *(float2*)&sq[head][2 * lane] = *(const float2*)(g_q + hb + (size_t)n * DH_ + 2 * lane);
    __syncwarp();
    int ih0 = min(max(hh - 2, 0), RESO - 5);
    int iw0 = min(max(ww - 2, 0), RESO - 5);
    float logit[3]; int nn[3];
#pragma unroll
    for (int s = 0; s < 3; s++) {
        int a = s * 32 + lane;
        logit[s] = -1e30f; nn[s] = 0;
        if (a < 75) {
            int at = a / 25, r = a % 25, ah = r / 5, aw = r % 5;
            int np = at * HW + (ih0 + ah) * RESO + (iw0 + aw);
            nn[s] = np;
            const float* kp = g_k + hb + (size_t)np * DH_;
            float d = 0.f;
#pragma unroll
            for (int j4 = 0; j4 < 12; j4++) {
                float4 kvv = *(const float4*)(kp + j4 * 4);
                d += kvv.x * sq[head][j4 * 4 + 0] + kvv.y * sq[head][j4 * 4 + 1]
                   + kvv.z * sq[head][j4 * 4 + 2] + kvv.w * sq[head][j4 * 4 + 3];
            }
            logit[s] = d;
        }
    }
    float m = fmaxf(fmaxf(logit[0], logit[1]), logit[2]);
#pragma unroll
    for (int o = 16; o; o >>= 1) m = fmaxf(m, __shfl_xor_sync(~0u, m, o));
    float p[3];
    p[0] = expf(logit[0] - m);
    p[1] = expf(logit[1] - m);
    p[2] = expf(logit[2] - m);
    float ssum = p[0] + p[1] + p[2];
#pragma unroll
    for (int o = 16; o; o >>= 1) ssum += __shfl_xor_sync(~0u, ssum, o);
    float inv = 1.f / ssum;
    float o0 = 0.f, o1 = 0.f;
#pragma unroll
    for (int s = 0; s < 3; s++) {
        int lim = (s == 2) ? 11 : 32;
        for (int src = 0; src < lim; src++) {
            float pa = __shfl_sync(~0u, p[s], src);
            int  np = __shfl_sync(~0u, nn[s], src);
            const float* vp = g_v + hb + (size_t)np * DH_;
            o0 += pa * vp[lane];
            if (lane < 16) o1 += pa * vp[lane + 32];
        }
    }
    float* xp = g_xa + (size_t)n * DIM_ + head * DH_;
    xp[lane] = o0 * inv;
    if (lane < 16) xp[lane + 32] = o1 * inv;
}

// ---------------- kernel 6: out = skip + xa@W_out + silu(mlp)@W_mlp + b_mlp ---
// A = [xa (768) | silu(fused[:,2304:]) (3072)], B = [W_out ; W_mlp], K=3840
__global__ void __launch_bounds__(256) k_gemm2(const float* __restrict__ Wo,
                                               const float* __restrict__ Wm,
                                               const float* __restrict__ bm_,
                                               const float* __restrict__ x,
                                               float* __restrict__ out) {
    __shared__ float As[16][68];
    __shared__ float Bs[16][128];
    int bm = blockIdx.y * 64, bn = blockIdx.x * 128;
    int tid = threadIdx.x;
    int tx = tid & 15, ty = tid >> 4;
    float acc[4][8];
#pragma unroll
    for (int i = 0; i < 4; i++)
#pragma unroll
        for (int j = 0; j < 8; j++) acc[i][j] = 0.f;

    int am = tid >> 2, ak4 = tid & 3;
    for (int k0 = 0; k0 < DIM_ + MLP_; k0 += 16) {
        float4 a;
        if (k0 < DIM_) {
            a = *(const float4*)(g_xa + (size_t)(bm + am) * DIM_ + k0 + ak4 * 4);
        } else {
            a = *(const float4*)(g_fused + (size_t)(bm + am) * FUSED_N + 3 * DIM_ +
                                 (k0 - DIM_) + ak4 * 4);
            a.x = silu_f(a.x); a.y = silu_f(a.y); a.z = silu_f(a.z); a.w = silu_f(a.w);
        }
        As[ak4 * 4 + 0][am] = a.x;
        As[ak4 * 4 + 1][am] = a.y;
        As[ak4 * 4 + 2][am] = a.z;
        As[ak4 * 4 + 3][am] = a.w;
#pragma unroll
        for (int p = 0; p < 2; p++) {
            int idx = tid + p * 256;
            int r = idx >> 5, c4 = idx & 31;
            const float* src = (k0 < DIM_)
                ? (Wo + (size_t)(k0 + r) * DIM_ + bn + c4 * 4)
                : (Wm + (size_t)(k0 - DIM_ + r) * DIM_ + bn + c4 * 4);
            *(float4*)&Bs[r][c4 * 4] = *(const float4*)src;
        }
        __syncthreads();
#pragma unroll
        for (int k = 0; k < 16; k++) {
            float4 av = *(const float4*)&As[k][ty * 4];
            float4 b0 = *(const float4*)&Bs[k][tx * 8];
            float4 b1 = *(const float4*)&Bs[k][tx * 8 + 4];
            float aa[4] = {av.x, av.y, av.z, av.w};
            float bb[8] = {b0.x, b0.y, b0.z, b0.w, b1.x, b1.y, b1.z, b1.w};
#pragma unroll
            for (int i = 0; i < 4; i++)
#pragma unroll
                for (int j = 0; j < 8; j++) acc[i][j] += aa[i] * bb[j];
        }
        __syncthreads();
    }
#pragma unroll
    for (int i = 0; i < 4; i++) {
        int n = bm + ty * 4 + i;
        int t = n / HW, hw = n % HW;
#pragma unroll
        for (int j = 0; j < 8; j++) {
            int c = bn + tx * 8 + j;
            size_t oi = ((size_t)t * DIM_ + c) * HW + hw;
            out[oi] = x[oi] + acc[i][j] + bm_[c];
        }
    }
}

// ---------------------------------- launcher ----------------------------------
extern "C" void kernel_launch(void* const* d_in, const int* in_sizes, int n_in,
                              void* d_out, int out_size) {
    const float* x       = (const float*)d_in[0];
    const float* emb     = (const float*)d_in[1];
    const float* w_mod   = (const float*)d_in[2];
    const float* b_mod   = (const float*)d_in[3];
    const float* qn_w    = (const float*)d_in[4];
    const float* qn_b    = (const float*)d_in[5];
    const float* kn_w    = (const float*)d_in[6];
    const float* kn_b    = (const float*)d_in[7];
    const float* W_fused = (const float*)d_in[8];
    const float* b_fused = (const float*)d_in[9];
    const float* W_out   = (const float*)d_in[10];
    const float* W_mlp   = (const float*)d_in[11];
    const float* b_mlp   = (const float*)d_in[12];
    float* out = (float*)d_out;

    k_mod<<<dim3(6, 3), 256>>>(emb, w_mod, b_mod);
    k_ln<<<NTOK, 256>>>(x);
    k_gemm1<<<dim3(FUSED_N / 128, NTOK / 64), 256>>>(W_fused, b_fused);
    k_qkv<<<NTOK, 512>>>(qn_w, qn_b, kn_w, kn_b);
    k_attn<<<NTOK, 512>>>();
    k_gemm2<<<dim3(DIM_ / 128, NTOK / 64), 256>>>(W_out, W_mlp, b_mlp, x, out);
}

// round 6
// speedup vs baseline: 1.8339x; 1.8339x over previous
#include <cuda_runtime.h>
#include <math.h>

#define T_      3
#define RESO    24
#define DIM_    768
#define HEADS_  16
#define DH_     48
#define EMB_    1024
#define MLP_    3072
#define HW      576              // RESO*RESO
#define NTOK    1728             // T_*HW
#define FUSED_N 5376             // 3*DIM_ + MLP_
#define EPS_    1e-5f
#define NSPLIT  8
#define KC2     480              // (DIM_+MLP_)/NSPLIT

// ---------------- scratch (device globals; no runtime allocation) -------------
__device__ float g_mod[T_ * 2 * DIM_];
__device__ float g_h[NTOK * DIM_];
__device__ float g_fused[(size_t)NTOK * FUSED_N];
__device__ float g_q[HEADS_ * NTOK * DH_];
__device__ float g_k[HEADS_ * NTOK * DH_];
__device__ float g_v[HEADS_ * NTOK * DH_];
__device__ float g_xa[NTOK * DIM_];
__device__ float g_part[(size_t)NSPLIT * NTOK * DIM_];   // split-K partials

__device__ __forceinline__ float silu_f(float x) { return x / (1.f + expf(-x)); }

// ---------------- f32x2 packed math helpers -----------------------------------
typedef unsigned long long ull;

__device__ __forceinline__ ull fma2(ull a, ull b, ull c) {
    ull d;
    asm("fma.rn.f32x2 %0, %1, %2, %3;" : "=l"(d) : "l"(a), "l"(b), "l"(c));
    return d;
}
__device__ __forceinline__ ull dup2(float x) {
    ull d;
    asm("mov.b64 %0, {%1, %2};" : "=l"(d) : "f"(x), "f"(x));
    return d;
}
__device__ __forceinline__ float2 up2(ull v) {
    return make_float2(__uint_as_float((unsigned)v),
                       __uint_as_float((unsigned)(v >> 32)));
}
__device__ __forceinline__ void cpa16(unsigned dst, const void* src) {
    asm volatile("cp.async.cg.shared.global [%0], [%1], 16;" :: "r"(dst), "l"(src));
}
#define CP_COMMIT() asm volatile("cp.async.commit_group;" ::: "memory")
#define CP_WAIT0()  asm volatile("cp.async.wait_group 0;" ::: "memory")

// ---------------- kernel 1: mod = silu(emb) @ w_mod + b_mod (3x1536) ----------
__global__ void k_mod(const float* __restrict__ emb,
                      const float* __restrict__ w_mod,
                      const float* __restrict__ b_mod) {
    __shared__ float se[EMB_];
    int t = blockIdx.y;
    for (int i = threadIdx.x; i < EMB_; i += 256)
        se[i] = silu_f(emb[t * EMB_ + i]);
    __syncthreads();
    int j = blockIdx.x * 256 + threadIdx.x;
    float acc = b_mod[j];
#pragma unroll 4
    for (int e = 0; e < EMB_; e++)
        acc += se[e] * w_mod[e * (2 * DIM_) + j];
    g_mod[t * (2 * DIM_) + j] = acc;
}

// ---------------- kernel 2: h = LN(x) * (1+scale) + shift ---------------------
__global__ void k_ln(const float* __restrict__ x) {
    int n = blockIdx.x;
    int t = n / HW, hw = n % HW;
    const float* xp = x + (size_t)t * DIM_ * HW + hw;
    int c0 = threadIdx.x, c1 = c0 + 256, c2 = c0 + 512;
    float v0 = xp[(size_t)c0 * HW];
    float v1 = xp[(size_t)c1 * HW];
    float v2 = xp[(size_t)c2 * HW];
    float s  = v0 + v1 + v2;
    float sq = v0 * v0 + v1 * v1 + v2 * v2;
    __shared__ float rs[8], rq[8];
#pragma unroll
    for (int o = 16; o; o >>= 1) {
        s  += __shfl_xor_sync(~0u, s, o);
        sq += __shfl_xor_sync(~0u, sq, o);
    }
    int wid = threadIdx.x >> 5, lid = threadIdx.x & 31;
    if (lid == 0) { rs[wid] = s; rq[wid] = sq; }
    __syncthreads();
    if (threadIdx.x == 0) {
        float ts = 0.f, tq = 0.f;
        for (int i = 0; i < 8; i++) { ts += rs[i]; tq += rq[i]; }
        rs[0] = ts; rq[0] = tq;
    }
    __syncthreads();
    float mean = rs[0] * (1.f / DIM_);
    float var  = rq[0] * (1.f / DIM_) - mean * mean;
    float inv  = rsqrtf(var + EPS_);
    const float* md = g_mod + t * (2 * DIM_);
    float* hp = g_h + (size_t)n * DIM_;
    hp[c0] = (v0 - mean) * inv * (1.f + md[c0]) + md[DIM_ + c0];
    hp[c1] = (v1 - mean) * inv * (1.f + md[c1]) + md[DIM_ + c1];
    hp[c2] = (v2 - mean) * inv * (1.f + md[c2]) + md[DIM_ + c2];
}

// ---------------- kernel 3: fused = h @ W_fused + b_fused ---------------------
// M=1728 K=768 N=5376. BM=64 BN=256 BK=16, 256 thr, 8x8/thread via f32x2.
__global__ void __launch_bounds__(256, 2) k_gemm1(const float* __restrict__ Wf,
                                                  const float* __restrict__ bf) {
    __shared__ float As[2][16][68];
    __shared__ float Bs[2][16][256];
    const int bm = blockIdx.y * 64, bn = blockIdx.x * 256;
    const int tid = threadIdx.x;
    const int ty = tid >> 5, tx = tid & 31;          // rows ty*8, cols tx*8
    const int arow = tid >> 2, ak = (tid & 3) * 4;   // A load: float4

    ull acc[8][4];
#pragma unroll
    for (int i = 0; i < 8; i++)
#pragma unroll
        for (int j = 0; j < 4; j++) acc[i][j] = 0ull;

    // ---- prologue: fill buffer 0
    {
        float4 a = *(const float4*)(g_h + (size_t)(bm + arow) * DIM_ + ak);
        As[0][ak + 0][arow] = a.x;
        As[0][ak + 1][arow] = a.y;
        As[0][ak + 2][arow] = a.z;
        As[0][ak + 3][arow] = a.w;
#pragma unroll
        for (int p = 0; p < 4; p++) {
            int lin = p * 256 + tid;
            int r = lin >> 6, c4 = (lin & 63) * 4;
            cpa16((unsigned)__cvta_generic_to_shared(&Bs[0][r][c4]),
                  Wf + (size_t)r * FUSED_N + bn + c4);
        }
        CP_COMMIT(); CP_WAIT0();
    }
    __syncthreads();

    const int nb = DIM_ / 16;   // 48
    for (int blk = 0; blk < nb; blk++) {
        int cur = blk & 1, nxt = cur ^ 1;
        float4 aReg;
        if (blk + 1 < nb) {
            int k0 = (blk + 1) * 16;
            aReg = *(const float4*)(g_h + (size_t)(bm + arow) * DIM_ + k0 + ak);
#pragma unroll
            for (int p = 0; p < 4; p++) {
                int lin = p * 256 + tid;
                int r = lin >> 6, c4 = (lin & 63) * 4;
                cpa16((unsigned)__cvta_generic_to_shared(&Bs[nxt][r][c4]),
                      Wf + (size_t)(k0 + r) * FUSED_N + bn + c4);
            }
            CP_COMMIT();
        }
#pragma unroll
        for (int k = 0; k < 16; k++) {
            float4 a0 = *(const float4*)&As[cur][k][ty * 8];
            float4 a1 = *(const float4*)&As[cur][k][ty * 8 + 4];
            ulonglong2 b0 = *(const ulonglong2*)&Bs[cur][k][tx * 8];
            ulonglong2 b1 = *(const ulonglong2*)&Bs[cur][k][tx * 8 + 4];
            ull av[8] = {dup2(a0.x), dup2(a0.y), dup2(a0.z), dup2(a0.w),
                         dup2(a1.x), dup2(a1.y), dup2(a1.z), dup2(a1.w)};
            ull bv[4] = {b0.x, b0.y, b1.x, b1.y};
#pragma unroll
            for (int i = 0; i < 8; i++)
#pragma unroll
                for (int j = 0; j < 4; j++) acc[i][j] = fma2(av[i], bv[j], acc[i][j]);
        }
        if (blk + 1 < nb) {
            As[nxt][ak + 0][arow] = aReg.x;
            As[nxt][ak + 1][arow] = aReg.y;
            As[nxt][ak + 2][arow] = aReg.z;
            As[nxt][ak + 3][arow] = aReg.w;
            CP_WAIT0();
        }
        __syncthreads();
    }

    // epilogue: + bias, store
    float bias[8];
#pragma unroll
    for (int j = 0; j < 8; j++) bias[j] = bf[bn + tx * 8 + j];
#pragma unroll
    for (int i = 0; i < 8; i++) {
        size_t off = (size_t)(bm + ty * 8 + i) * FUSED_N + bn + tx * 8;
        float2 p0 = up2(acc[i][0]), p1 = up2(acc[i][1]);
        float2 p2 = up2(acc[i][2]), p3 = up2(acc[i][3]);
        float4 o0 = make_float4(p0.x + bias[0], p0.y + bias[1],
                                p1.x + bias[2], p1.y + bias[3]);
        float4 o1 = make_float4(p2.x + bias[4], p2.y + bias[5],
                                p3.x + bias[6], p3.y + bias[7]);
        *(float4*)(g_fused + off)     = o0;
        *(float4*)(g_fused + off + 4) = o1;
    }
}

// ---------------- kernel 4: qk-norm + RoPE + scatter q/k/v --------------------
__global__ void __launch_bounds__(512) k_qkv(const float* __restrict__ qn_w,
                                             const float* __restrict__ qn_b,
                                             const float* __restrict__ kn_w,
                                             const float* __restrict__ kn_b) {
    int n = blockIdx.x;
    int head = threadIdx.x >> 5;
    int lane = threadIdx.x & 31;
    int t = n / HW, hh = (n % HW) / RESO, ww = n % RESO;
    const float* fp = g_fused + (size_t)n * FUSED_N + head * DH_;
    float2 q2 = make_float2(0.f, 0.f), k2 = q2, v2 = q2;
    if (lane < 24) {
        q2 = *(const float2*)(fp + 2 * lane);
        k2 = *(const float2*)(fp + DIM_ + 2 * lane);
        v2 = *(const float2*)(fp + 2 * DIM_ + 2 * lane);
    }
    float qs = q2.x + q2.y, qq = q2.x * q2.x + q2.y * q2.y;
    float ks = k2.x + k2.y, kq = k2.x * k2.x + k2.y * k2.y;
#pragma unroll
    for (int o = 16; o; o >>= 1) {
        qs += __shfl_xor_sync(~0u, qs, o);
        qq += __shfl_xor_sync(~0u, qq, o);
        ks += __shfl_xor_sync(~0u, ks, o);
        kq += __shfl_xor_sync(~0u, kq, o);
    }
    if (lane < 24) {
        float qm = qs * (1.f / DH_), qv = qq * (1.f / DH_) - qm * qm;
        float km = ks * (1.f / DH_), kv = kq * (1.f / DH_) - km * km;
        float qi = rsqrtf(qv + EPS_), ki = rsqrtf(kv + EPS_);
        int j0 = 2 * lane, j1 = j0 + 1;
        float qn0 = (q2.x - qm) * qi * qn_w[j0] + qn_b[j0];
        float qn1 = (q2.y - qm) * qi * qn_w[j1] + qn_b[j1];
        float kn0 = (k2.x - km) * ki * kn_w[j0] + kn_b[j0];
        float kn1 = (k2.y - km) * ki * kn_w[j1] + kn_b[j1];
        int i = lane;
        int idx;  float pos;
        if (i < 8)       { idx = i;      pos = (float)t;  }
        else if (i < 16) { idx = i - 8;  pos = (float)hh; }
        else             { idx = i - 16; pos = (float)ww; }
        float ang = pos * powf(10000.f, -(float)idx * 0.125f);
        float c = cosf(ang), sn = sinf(ang);
        const float qsc = 0.14433756729740643f;  // 48^-0.5
        size_t base = ((size_t)head * NTOK + n) * DH_;
        *(float2*)(g_q + base + j0) =
            make_float2((qn0 * c - qn1 * sn) * qsc, (qn0 * sn + qn1 * c) * qsc);
        *(float2*)(g_k + base + j0) =
            make_float2(kn0 * c - kn1 * sn, kn0 * sn + kn1 * c);
        *(float2*)(g_v + base + j0) = v2;
    }
}

// ---------------- kernel 5: neighborhood attention (75 nbrs) ------------------
__global__ void __launch_bounds__(512) k_attn() {
    __shared__ float sq[HEADS_][DH_];
    int n = blockIdx.x;
    int head = threadIdx.x >> 5, lane = threadIdx.x & 31;
    int hh = (n % HW) / RESO, ww = n % RESO;
    size_t hb = (size_t)head * NTOK * DH_;
    if (lane < 24)
        *(float2*)&sq[head][2 * lane] = *(const float2*)(g_q + hb + (size_t)n * DH_ + 2 * lane);
    __syncwarp();
    int ih0 = min(max(hh - 2, 0), RESO - 5);
    int iw0 = min(max(ww - 2, 0), RESO - 5);
    float logit[3]; int nn[3];
#pragma unroll
    for (int s = 0; s < 3; s++) {
        int a = s * 32 + lane;
        logit[s] = -1e30f; nn[s] = 0;
        if (a < 75) {
            int at = a / 25, r = a % 25, ah = r / 5, aw = r % 5;
            int np = at * HW + (ih0 + ah) * RESO + (iw0 + aw);
            nn[s] = np;
            const float* kp = g_k + hb + (size_t)np * DH_;
            float d = 0.f;
#pragma unroll
            for (int j4 = 0; j4 < 12; j4++) {
                float4 kvv = *(const float4*)(kp + j4 * 4);
                d += kvv.x * sq[head][j4 * 4 + 0] + kvv.y * sq[head][j4 * 4 + 1]
                   + kvv.z * sq[head][j4 * 4 + 2] + kvv.w * sq[head][j4 * 4 + 3];
            }
            logit[s] = d;
        }
    }
    float m = fmaxf(fmaxf(logit[0], logit[1]), logit[2]);
#pragma unroll
    for (int o = 16; o; o >>= 1) m = fmaxf(m, __shfl_xor_sync(~0u, m, o));
    float p[3];
    p[0] = expf(logit[0] - m);
    p[1] = expf(logit[1] - m);
    p[2] = expf(logit[2] - m);
    float ssum = p[0] + p[1] + p[2];
#pragma unroll
    for (int o = 16; o; o >>= 1) ssum += __shfl_xor_sync(~0u, ssum, o);
    float inv = 1.f / ssum;
    float o0 = 0.f, o1 = 0.f;
#pragma unroll
    for (int s = 0; s < 3; s++) {
        int lim = (s == 2) ? 11 : 32;
        for (int src = 0; src < lim; src++) {
            float pa = __shfl_sync(~0u, p[s], src);
            int  np = __shfl_sync(~0u, nn[s], src);
            const float* vp = g_v + hb + (size_t)np * DH_;
            o0 += pa * vp[lane];
            if (lane < 16) o1 += pa * vp[lane + 32];
        }
    }
    float* xp = g_xa + (size_t)n * DIM_ + head * DH_;
    xp[lane] = o0 * inv;
    if (lane < 16) xp[lane + 32] = o1 * inv;
}

// ---------------- kernel 6: split-K GEMM for out-proj + MLP-down --------------
// A = [xa(768) | silu(fused[:,2304:])(3072)], B = [W_out; W_mlp], K=3840.
// BM=64 BN=128 BK=16, split-K=8 (480 per split). Partials -> g_part.
__global__ void __launch_bounds__(256) k_gemm2(const float* __restrict__ Wo,
                                               const float* __restrict__ Wm) {
    __shared__ float As[2][16][68];
    __shared__ float Bs[2][16][128];
    const int bm = blockIdx.y * 64, bn = blockIdx.x * 128;
    const int kc = blockIdx.z;
    const int tid = threadIdx.x;
    const int ty = tid >> 5, tx = tid & 31;          // rows ty*8, cols tx*4
    const int arow = tid >> 2, ak = (tid & 3) * 4;

    ull acc[8][2];
#pragma unroll
    for (int i = 0; i < 8; i++) { acc[i][0] = 0ull; acc[i][1] = 0ull; }

    const float* arowp_xa = g_xa + (size_t)(bm + arow) * DIM_;
    const float* arowp_ml = g_fused + (size_t)(bm + arow) * FUSED_N + 3 * DIM_ - DIM_;
    // (arowp_ml + kg) valid for kg>=768: offset 2304 + (kg-768) = 1536 + kg

    // ---- prologue buffer 0
    {
        int kg = kc * KC2 + ak;
        float4 a;
        if (kg < DIM_) a = *(const float4*)(arowp_xa + kg);
        else {
            a = *(const float4*)(arowp_ml + kg);
            a.x = silu_f(a.x); a.y = silu_f(a.y); a.z = silu_f(a.z); a.w = silu_f(a.w);
        }
        As[0][ak + 0][arow] = a.x;
        As[0][ak + 1][arow] = a.y;
        As[0][ak + 2][arow] = a.z;
        As[0][ak + 3][arow] = a.w;
#pragma unroll
        for (int p = 0; p < 2; p++) {
            int lin = p * 256 + tid;
            int r = lin >> 5, c4 = (lin & 31) * 4;
            int krow = kc * KC2 + r;
            const float* src = (krow < DIM_)
                ? (Wo + (size_t)krow * DIM_ + bn + c4)
                : (Wm + (size_t)(krow - DIM_) * DIM_ + bn + c4);
            cpa16((unsigned)__cvta_generic_to_shared(&Bs[0][r][c4]), src);
        }
        CP_COMMIT(); CP_WAIT0();
    }
    __syncthreads();

    const int nb = KC2 / 16;   // 30
    for (int blk = 0; blk < nb; blk++) {
        int cur = blk & 1, nxt = cur ^ 1;
        float4 aReg; bool sil = false;
        if (blk + 1 < nb) {
            int k0 = kc * KC2 + (blk + 1) * 16;
            int kg = k0 + ak;
            if (kg < DIM_) aReg = *(const float4*)(arowp_xa + kg);
            else { aReg = *(const float4*)(arowp_ml + kg); sil = true; }
#pragma unroll
            for (int p = 0; p < 2; p++) {
                int lin = p * 256 + tid;
                int r = lin >> 5, c4 = (lin & 31) * 4;
                int krow = k0 + r;
                const float* src = (krow < DIM_)
                    ? (Wo + (size_t)krow * DIM_ + bn + c4)
                    : (Wm + (size_t)(krow - DIM_) * DIM_ + bn + c4);
                cpa16((unsigned)__cvta_generic_to_shared(&Bs[nxt][r][c4]), src);
            }
            CP_COMMIT();
        }
#pragma unroll
        for (int k = 0; k < 16; k++) {
            float4 a0 = *(const float4*)&As[cur][k][ty * 8];
            float4 a1 = *(const float4*)&As[cur][k][ty * 8 + 4];
            ulonglong2 b0 = *(const ulonglong2*)&Bs[cur][k][tx * 4];
            ull av[8] = {dup2(a0.x), dup2(a0.y), dup2(a0.z), dup2(a0.w),
                         dup2(a1.x), dup2(a1.y), dup2(a1.z), dup2(a1.w)};
#pragma unroll
            for (int i = 0; i < 8; i++) {
                acc[i][0] = fma2(av[i], b0.x, acc[i][0]);
                acc[i][1] = fma2(av[i], b0.y, acc[i][1]);
            }
        }
        if (blk + 1 < nb) {
            if (sil) { aReg.x = silu_f(aReg.x); aReg.y = silu_f(aReg.y);
                       aReg.z = silu_f(aReg.z); aReg.w = silu_f(aReg.w); }
            As[nxt][ak + 0][arow] = aReg.x;
            As[nxt][ak + 1][arow] = aReg.y;
            As[nxt][ak + 2][arow] = aReg.z;
            As[nxt][ak + 3][arow] = aReg.w;
            CP_WAIT0();
        }
        __syncthreads();
    }

#pragma unroll
    for (int i = 0; i < 8; i++) {
        size_t off = ((size_t)kc * NTOK + bm + ty * 8 + i) * DIM_ + bn + tx * 4;
        float2 p0 = up2(acc[i][0]), p1 = up2(acc[i][1]);
        *(float4*)(g_part + off) = make_float4(p0.x, p0.y, p1.x, p1.y);
    }
}

// ---------------- kernel 7: reduce partials + skip + bias + transpose ---------
// out[(t*768+c)*576+hw] = x[...] + sum_z part[z][t*576+hw][c] + b_mlp[c]
__global__ void __launch_bounds__(256) k_fin(const float* __restrict__ x,
                                             const float* __restrict__ bm_,
                                             float* __restrict__ out) {
    __shared__ float s[32][33];
    int hw0 = blockIdx.x * 32, c0 = blockIdx.y * 32, t = blockIdx.z;
    int lx = threadIdx.x & 31, lyb = threadIdx.x >> 5;   // 32 x 8
#pragma unroll
    for (int r = 0; r < 4; r++) {
        int hwl = lyb + r * 8;
        int c = c0 + lx;
        size_t nidx = ((size_t)(t * HW + hw0 + hwl)) * DIM_ + c;
        float sum = bm_[c];
#pragma unroll
        for (int z = 0; z < NSPLIT; z++)
            sum += g_part[(size_t)z * NTOK * DIM_ + nidx];
        s[hwl][lx] = sum;
    }
    __syncthreads();
#pragma unroll
    for (int r = 0; r < 4; r++) {
        int cl = lyb + r * 8;
        size_t oi = ((size_t)(t * DIM_ + c0 + cl)) * HW + hw0 + lx;
        out[oi] = x[oi] + s[lx][cl];
    }
}

// ---------------------------------- launcher ----------------------------------
extern "C" void kernel_launch(void* const* d_in, const int* in_sizes, int n_in,
                              void* d_out, int out_size) {
    const float* x       = (const float*)d_in[0];
    const float* emb     = (const float*)d_in[1];
    const float* w_mod   = (const float*)d_in[2];
    const float* b_mod   = (const float*)d_in[3];
    const float* qn_w    = (const float*)d_in[4];
    const float* qn_b    = (const float*)d_in[5];
    const float* kn_w    = (const float*)d_in[6];
    const float* kn_b    = (const float*)d_in[7];
    const float* W_fused = (const float*)d_in[8];
    const float* b_fused = (const float*)d_in[9];
    const float* W_out   = (const float*)d_in[10];
    const float* W_mlp   = (const float*)d_in[11];
    const float* b_mlp   = (const float*)d_in[12];
    float* out = (float*)d_out;

    k_mod<<<dim3(6, 3), 256>>>(emb, w_mod, b_mod);
    k_ln<<<NTOK, 256>>>(x);
    k_gemm1<<<dim3(FUSED_N / 256, NTOK / 64), 256>>>(W_fused, b_fused);
    k_qkv<<<NTOK, 512>>>(qn_w, qn_b, kn_w, kn_b);
    k_attn<<<NTOK, 512>>>();
    k_gemm2<<<dim3(DIM_ / 128, NTOK / 64, NSPLIT), 256>>>(W_out, W_mlp);
    k_fin<<<dim3(RESO * RESO / 32, DIM_ / 32, T_), 256>>>(x, b_mlp, out);
}

// round 9
// speedup vs baseline: 2.5226x; 1.3755x over previous
#include <cuda_runtime.h>
#include <math.h>
#include <stdint.h>

#define T_      3
#define RESO    24
#define DIM_    768
#define HEADS_  16
#define DH_     48
#define EMB_    1024
#define MLP_    3072
#define HW      576
#define NTOK    1728
#define FUSED_N 5376
#define K2TOT   3840
#define EPS_    1e-5f
#define NSPLIT  4
#define KSPLIT2 960              // K2TOT / NSPLIT
#define LDA     36               // padded row stride (floats)
#define TILE_F  (128 * LDA)      // floats per tile buffer
#define SMEM_BYTES (2 * TILE_F * 2 * 4)   // 2 bufs x (A+B) x 4B = 73728

// ---------------- scratch ------------------------------------------------------
__device__ float g_mod[T_ * 2 * DIM_];
__device__ float g_h[NTOK * DIM_];
__device__ float g_fused[(size_t)NTOK * FUSED_N];
__device__ float g_q[HEADS_ * NTOK * DH_];
__device__ float g_k[HEADS_ * NTOK * DH_];
__device__ float g_v[HEADS_ * NTOK * DH_];
__device__ float g_xa[NTOK * DIM_];
__device__ float g_part[(size_t)NSPLIT * NTOK * DIM_];
__device__ float g_wt1[(size_t)FUSED_N * DIM_];   // W_fused^T [5376][768], tf32-rounded
__device__ float g_wt2[(size_t)DIM_ * K2TOT];     // [W_out^T | W_mlp^T] [768][3840], tf32-rounded

__device__ __forceinline__ float silu_f(float x) { return x / (1.f + expf(-x)); }

__device__ __forceinline__ float tf32r(float x) {
    uint32_t r;
    asm("cvt.rna.tf32.f32 %0, %1;" : "=r"(r) : "f"(x));
    return __uint_as_float(r);
}
__device__ __forceinline__ void cpa16(unsigned dst, const void* src) {
    asm volatile("cp.async.cg.shared.global [%0], [%1], 16;" :: "r"(dst), "l"(src));
}
#define CP_COMMIT() asm volatile("cp.async.commit_group;" ::: "memory")
#define CP_WAIT0()  asm volatile("cp.async.wait_group 0;" ::: "memory")

__device__ __forceinline__ void mma_tf32(float* d,
                                         uint32_t a0, uint32_t a1, uint32_t a2, uint32_t a3,
                                         uint32_t b0, uint32_t b1) {
    asm volatile(
        "mma.sync.aligned.m16n8k8.row.col.f32.tf32.tf32.f32 "
        "{%0,%1,%2,%3}, {%4,%5,%6,%7}, {%8,%9}, {%0,%1,%2,%3};"
        : "+f"(d[0]), "+f"(d[1]), "+f"(d[2]), "+f"(d[3])
        : "r"(a0), "r"(a1), "r"(a2), "r"(a3), "r"(b0), "r"(b1));
}

// ---------------- kernel: transpose + tf32 round  dst[n][koff+k] = src[k][n] ---
__global__ void __launch_bounds__(256) k_tr(const float* __restrict__ src,
                                            float* __restrict__ dst,
                                            int N, int dld, int koff) {
    __shared__ float ts[32][33];
    int k0 = blockIdx.y * 32, n0 = blockIdx.x * 32;
    int lx = threadIdx.x & 31, ly = threadIdx.x >> 5;
#pragma unroll
    for (int r = 0; r < 4; r++)
        ts[ly + r * 8][lx] = src[(size_t)(k0 + ly + r * 8) * N + n0 + lx];
    __syncthreads();
#pragma unroll
    for (int r = 0; r < 4; r++)
        dst[(size_t)(n0 + ly + r * 8) * dld + koff + k0 + lx] = tf32r(ts[lx][ly + r * 8]);
}

// ---------------- kernel 1: mod = silu(emb) @ w_mod + b_mod -------------------
__global__ void k_mod(const float* __restrict__ emb,
                      const float* __restrict__ w_mod,
                      const float* __restrict__ b_mod) {
    __shared__ float se[EMB_];
    int t = blockIdx.y;
    for (int i = threadIdx.x; i < EMB_; i += 256)
        se[i] = silu_f(emb[t * EMB_ + i]);
    __syncthreads();
    int j = blockIdx.x * 256 + threadIdx.x;
    float acc = b_mod[j];
#pragma unroll 4
    for (int e = 0; e < EMB_; e++)
        acc += se[e] * w_mod[e * (2 * DIM_) + j];
    g_mod[t * (2 * DIM_) + j] = acc;
}

// ---------------- kernel 2: h = LN(x)*(1+scale)+shift, tf32-rounded -----------
__global__ void k_ln(const float* __restrict__ x) {
    int n = blockIdx.x;
    int t = n / HW, hw = n % HW;
    const float* xp = x + (size_t)t * DIM_ * HW + hw;
    int c0 = threadIdx.x, c1 = c0 + 256, c2 = c0 + 512;
    float v0 = xp[(size_t)c0 * HW];
    float v1 = xp[(size_t)c1 * HW];
    float v2 = xp[(size_t)c2 * HW];
    float s  = v0 + v1 + v2;
    float sq = v0 * v0 + v1 * v1 + v2 * v2;
    __shared__ float rs[8], rq[8];
#pragma unroll
    for (int o = 16; o; o >>= 1) {
        s  += __shfl_xor_sync(~0u, s, o);
        sq += __shfl_xor_sync(~0u, sq, o);
    }
    int wid = threadIdx.x >> 5, lid = threadIdx.x & 31;
    if (lid == 0) { rs[wid] = s; rq[wid] = sq; }
    __syncthreads();
    if (threadIdx.x == 0) {
        float ts = 0.f, tq = 0.f;
        for (int i = 0; i < 8; i++) { ts += rs[i]; tq += rq[i]; }
        rs[0] = ts; rq[0] = tq;
    }
    __syncthreads();
    float mean = rs[0] * (1.f / DIM_);
    float var  = rq[0] * (1.f / DIM_) - mean * mean;
    float inv  = rsqrtf(var + EPS_);
    const float* md = g_mod + t * (2 * DIM_);
    float* hp = g_h + (size_t)n * DIM_;
    hp[c0] = tf32r((v0 - mean) * inv * (1.f + md[c0]) + md[DIM_ + c0]);
    hp[c1] = tf32r((v1 - mean) * inv * (1.f + md[c1]) + md[DIM_ + c1]);
    hp[c2] = tf32r((v2 - mean) * inv * (1.f + md[c2]) + md[DIM_ + c2]);
}

// ---------------- mma.sync tf32 GEMM 1: fused = h @ W_fused + b_fused ---------
// CTA 128x128, 8 warps (4m x 2n), warp tile 32x64, BK=32, double-buffer cp.async.
__global__ void __launch_bounds__(256, 2) k_gemm1_mma(const float* __restrict__ bf) {
    extern __shared__ uint32_t smu[];
    uint32_t* As = smu;                    // [2][128][LDA]
    uint32_t* Bs = smu + 2 * TILE_F;
    const int tid = threadIdx.x, wid = tid >> 5, lane = tid & 31;
    const int wm = wid & 3, wn = wid >> 2;
    const int g = lane >> 2, tig = lane & 3;
    const int bm = blockIdx.y * 128, bn = blockIdx.x * 256 / 2;  // grid.x covers N/128
    const int BN = blockIdx.x * 128;
    (void)bn;

    float acc[2][8][4];
#pragma unroll
    for (int a = 0; a < 2; a++)
#pragma unroll
        for (int b = 0; b < 8; b++)
#pragma unroll
            for (int c = 0; c < 4; c++) acc[a][b][c] = 0.f;

    const int lrow = tid >> 3, lc4 = (tid & 7) * 4;   // 4 iters cover 128 rows? no:
    // producer indexing: 256 thr x 4 chunks -> 1024 float4 = 128 rows x 8 f4 (x2 arrays)
#define A_OFF(buf, r, k) ((unsigned)__cvta_generic_to_shared(&As[((buf) * 128 + (r)) * LDA + (k)]))
#define B_OFF(buf, r, k) ((unsigned)__cvta_generic_to_shared(&Bs[((buf) * 128 + (r)) * LDA + (k)]))

    // prologue: buffer 0, k0 = 0
#pragma unroll
    for (int i = 0; i < 4; i++) {
        int lin = i * 256 + tid;
        int row = lin >> 3, c4 = (lin & 7) * 4;
        int r = min(bm + row, NTOK - 1);
        cpa16(A_OFF(0, row, c4), g_h + (size_t)r * DIM_ + c4);
        cpa16(B_OFF(0, row, c4), g_wt1 + (size_t)(BN + row) * DIM_ + c4);
    }
    CP_COMMIT(); CP_WAIT0();
    __syncthreads();

    const int NIT = DIM_ / 32;   // 24
    for (int kt = 0; kt < NIT; kt++) {
        int cur = kt & 1, nxt = cur ^ 1;
        if (kt + 1 < NIT) {
            int k0 = (kt + 1) * 32;
#pragma unroll
            for (int i = 0; i < 4; i++) {
                int lin = i * 256 + tid;
                int row = lin >> 3, c4 = (lin & 7) * 4;
                int r = min(bm + row, NTOK - 1);
                cpa16(A_OFF(nxt, row, c4), g_h + (size_t)r * DIM_ + k0 + c4);
                cpa16(B_OFF(nxt, row, c4), g_wt1 + (size_t)(BN + row) * DIM_ + k0 + c4);
            }
            CP_COMMIT();
        }
        const uint32_t* Ab = As + (size_t)cur * TILE_F;
        const uint32_t* Bb = Bs + (size_t)cur * TILE_F;
#pragma unroll
        for (int ks = 0; ks < 4; ks++) {
            int k0 = ks * 8;
            uint32_t af[2][4];
#pragma unroll
            for (int mb = 0; mb < 2; mb++) {
                int mr = wm * 32 + mb * 16 + g;
                af[mb][0] = Ab[mr * LDA + k0 + tig];
                af[mb][1] = Ab[(mr + 8) * LDA + k0 + tig];
                af[mb][2] = Ab[mr * LDA + k0 + tig + 4];
                af[mb][3] = Ab[(mr + 8) * LDA + k0 + tig + 4];
            }
#pragma unroll
            for (int nb = 0; nb < 8; nb++) {
                int nr = wn * 64 + nb * 8 + g;
                uint32_t b0 = Bb[nr * LDA + k0 + tig];
                uint32_t b1 = Bb[nr * LDA + k0 + tig + 4];
                mma_tf32(acc[0][nb], af[0][0], af[0][1], af[0][2], af[0][3], b0, b1);
                mma_tf32(acc[1][nb], af[1][0], af[1][1], af[1][2], af[1][3], b0, b1);
            }
        }
        if (kt + 1 < NIT) CP_WAIT0();
        __syncthreads();
    }

    // epilogue: bias + store
#pragma unroll
    for (int mb = 0; mb < 2; mb++) {
#pragma unroll
        for (int rr = 0; rr < 2; rr++) {
            int row = bm + wm * 32 + mb * 16 + rr * 8 + g;
            if (row >= NTOK) continue;
            float* dst = g_fused + (size_t)row * FUSED_N + BN + wn * 64;
#pragma unroll
            for (int nb = 0; nb < 8; nb++) {
                int col = nb * 8 + 2 * tig;
                float2 o;
                o.x = acc[mb][nb][rr * 2 + 0] + bf[BN + wn * 64 + col];
                o.y = acc[mb][nb][rr * 2 + 1] + bf[BN + wn * 64 + col + 1];
                *(float2*)(dst + col) = o;
            }
        }
    }
}

// ---------------- mma.sync tf32 GEMM 2: [xa|silu(mlp)] @ [Wo;Wm], split-K=4 ---
__global__ void __launch_bounds__(256, 2) k_gemm2_mma() {
    extern __shared__ uint32_t smu[];
    uint32_t* As = smu;
    uint32_t* Bs = smu + 2 * TILE_F;
    const int tid = threadIdx.x, wid = tid >> 5, lane = tid & 31;
    const int wm = wid & 3, wn = wid >> 2;
    const int g = lane >> 2, tig = lane & 3;
    const int bm = blockIdx.y * 128, BN = blockIdx.x * 128;
    const int z = blockIdx.z;
    const int kbase = z * KSPLIT2;

    float acc[2][8][4];
#pragma unroll
    for (int a = 0; a < 2; a++)
#pragma unroll
        for (int b = 0; b < 8; b++)
#pragma unroll
            for (int c = 0; c < 4; c++) acc[a][b][c] = 0.f;

    // A element fetch (manual: xa pre-rounded, or silu+round of mlp_h)
    auto loadA4 = [&](int row, int k) -> float4 {
        int r = min(bm + row, NTOK - 1);
        if (k < DIM_) {
            return *(const float4*)(g_xa + (size_t)r * DIM_ + k);
        } else {
            float4 v = *(const float4*)(g_fused + (size_t)r * FUSED_N + 1536 + k);
            v.x = tf32r(silu_f(v.x)); v.y = tf32r(silu_f(v.y));
            v.z = tf32r(silu_f(v.z)); v.w = tf32r(silu_f(v.w));
            return v;
        }
    };

    // prologue buffer 0
#pragma unroll
    for (int i = 0; i < 4; i++) {
        int lin = i * 256 + tid;
        int row = lin >> 3, c4 = (lin & 7) * 4;
        float4 v = loadA4(row, kbase + c4);
        *(float4*)&As[(0 * 128 + row) * LDA + c4] = *(float4*)&v;
        cpa16((unsigned)__cvta_generic_to_shared(&Bs[(0 * 128 + row) * LDA + c4]),
              g_wt2 + (size_t)(BN + row) * K2TOT + kbase + c4);
    }
    CP_COMMIT(); CP_WAIT0();
    __syncthreads();

    const int NIT = KSPLIT2 / 32;   // 30
    for (int kt = 0; kt < NIT; kt++) {
        int cur = kt & 1, nxt = cur ^ 1;
        float4 aReg[4];
        if (kt + 1 < NIT) {
            int k0 = kbase + (kt + 1) * 32;
#pragma unroll
            for (int i = 0; i < 4; i++) {
                int lin = i * 256 + tid;
                int row = lin >> 3, c4 = (lin & 7) * 4;
                aReg[i] = loadA4(row, k0 + c4);
                cpa16((unsigned)__cvta_generic_to_shared(&Bs[(nxt * 128 + row) * LDA + c4]),
                      g_wt2 + (size_t)(BN + row) * K2TOT + k0 + c4);
            }
            CP_COMMIT();
        }
        const uint32_t* Ab = As + (size_t)cur * TILE_F;
        const uint32_t* Bb = Bs + (size_t)cur * TILE_F;
#pragma unroll
        for (int ks = 0; ks < 4; ks++) {
            int k0 = ks * 8;
            uint32_t af[2][4];
#pragma unroll
            for (int mb = 0; mb < 2; mb++) {
                int mr = wm * 32 + mb * 16 + g;
                af[mb][0] = Ab[mr * LDA + k0 + tig];
                af[mb][1] = Ab[(mr + 8) * LDA + k0 + tig];
                af[mb][2] = Ab[mr * LDA + k0 + tig + 4];
                af[mb][3] = Ab[(mr + 8) * LDA + k0 + tig + 4];
            }
#pragma unroll
            for (int nb = 0; nb < 8; nb++) {
                int nr = wn * 64 + nb * 8 + g;
                uint32_t b0 = Bb[nr * LDA + k0 + tig];
                uint32_t b1 = Bb[nr * LDA + k0 + tig + 4];
                mma_tf32(acc[0][nb], af[0][0], af[0][1], af[0][2], af[0][3], b0, b1);
                mma_tf32(acc[1][nb], af[1][0], af[1][1], af[1][2], af[1][3], b0, b1);
            }
        }
        if (kt + 1 < NIT) {
#pragma unroll
            for (int i = 0; i < 4; i++) {
                int lin = i * 256 + tid;
                int row = lin >> 3, c4 = (lin & 7) * 4;
                *(float4*)&As[(nxt * 128 + row) * LDA + c4] = aReg[i];
            }
            CP_WAIT0();
        }
        __syncthreads();
    }

#pragma unroll
    for (int mb = 0; mb < 2; mb++) {
#pragma unroll
        for (int rr = 0; rr < 2; rr++) {
            int row = bm + wm * 32 + mb * 16 + rr * 8 + g;
            if (row >= NTOK) continue;
            float* dst = g_part + ((size_t)z * NTOK + row) * DIM_ + BN + wn * 64;
#pragma unroll
            for (int nb = 0; nb < 8; nb++) {
                int col = nb * 8 + 2 * tig;
                float2 o;
                o.x = acc[mb][nb][rr * 2 + 0];
                o.y = acc[mb][nb][rr * 2 + 1];
                *(float2*)(dst + col) = o;
            }
        }
    }
}

// ---------------- kernel 4: qk-norm + RoPE + scatter q/k/v --------------------
__global__ void __launch_bounds__(512) k_qkv(const float* __restrict__ qn_w,
                                             const float* __restrict__ qn_b,
                                             const float* __restrict__ kn_w,
                                             const float* __restrict__ kn_b) {
    int n = blockIdx.x;
    int head = threadIdx.x >> 5;
    int lane = threadIdx.x & 31;
    int t = n / HW, hh = (n % HW) / RESO, ww = n % RESO;
    const float* fp = g_fused + (size_t)n * FUSED_N + head * DH_;
    float2 q2 = make_float2(0.f, 0.f), k2 = q2, v2 = q2;
    if (lane < 24) {
        q2 = *(const float2*)(fp + 2 * lane);
        k2 = *(const float2*)(fp + DIM_ + 2 * lane);
        v2 = *(const float2*)(fp + 2 * DIM_ + 2 * lane);
    }
    float qs = q2.x + q2.y, qq = q2.x * q2.x + q2.y * q2.y;
    float ks = k2.x + k2.y, kq = k2.x * k2.x + k2.y * k2.y;
#pragma unroll
    for (int o = 16; o; o >>= 1) {
        qs += __shfl_xor_sync(~0u, qs, o);
        qq += __shfl_xor_sync(~0u, qq, o);
        ks += __shfl_xor_sync(~0u, ks, o);
        kq += __shfl_xor_sync(~0u, kq, o);
    }
    if (lane < 24) {
        float qm = qs * (1.f / DH_), qv = qq * (1.f / DH_) - qm * qm;
        float km = ks * (1.f / DH_), kv = kq * (1.f / DH_) - km * km;
        float qi = rsqrtf(qv + EPS_), ki = rsqrtf(kv + EPS_);
        int j0 = 2 * lane, j1 = j0 + 1;
        float qn0 = (q2.x - qm) * qi * qn_w[j0] + qn_b[j0];
        float qn1 = (q2.y - qm) * qi * qn_w[j1] + qn_b[j1];
        float kn0 = (k2.x - km) * ki * kn_w[j0] + kn_b[j0];
        float kn1 = (k2.y - km) * ki * kn_w[j1] + kn_b[j1];
        int i = lane;
        int idx;  float pos;
        if (i < 8)       { idx = i;      pos = (float)t;  }
        else if (i < 16) { idx = i - 8;  pos = (float)hh; }
        else             { idx = i - 16; pos = (float)ww; }
        float ang = pos * powf(10000.f, -(float)idx * 0.125f);
        float c = cosf(ang), sn = sinf(ang);
        const float qsc = 0.14433756729740643f;  // 48^-0.5
        size_t base = ((size_t)head * NTOK + n) * DH_;
        *(float2*)(g_q + base + j0) =
            make_float2((qn0 * c - qn1 * sn) * qsc, (qn0 * sn + qn1 * c) * qsc);
        *(float2*)(g_k + base + j0) =
            make_float2(kn0 * c - kn1 * sn, kn0 * sn + kn1 * c);
        *(float2*)(g_v + base + j0) = v2;
    }
}

// ---------------- kernel 5: neighborhood attention (75 nbrs) ------------------
__global__ void __launch_bounds__(512) k_attn() {
    __shared__ float sq[HEADS_][DH_];
    int n = blockIdx.x;
    int head = threadIdx.x >> 5, lane = threadIdx.x & 31;
    int hh = (n % HW) / RESO, ww = n % RESO;
    size_t hb = (size_t)head * NTOK * DH_;
    if (lane < 24)
        *(float2*)&sq[head][2 * lane] = *(const float2*)(g_q + hb + (size_t)n * DH_ + 2 * lane);
    __syncwarp();
    int ih0 = min(max(hh - 2, 0), RESO - 5);
    int iw0 = min(max(ww - 2, 0), RESO - 5);
    float logit[3]; int nn[3];
#pragma unroll
    for (int s = 0; s < 3; s++) {
        int a = s * 32 + lane;
        logit[s] = -1e30f; nn[s] = 0;
        if (a < 75) {
            int at = a / 25, r = a % 25, ah = r / 5, aw = r % 5;
            int np = at * HW + (ih0 + ah) * RESO + (iw0 + aw);
            nn[s] = np;
            const float* kp = g_k + hb + (size_t)np * DH_;
            float d = 0.f;
#pragma unroll
            for (int j4 = 0; j4 < 12; j4++) {
                float4 kvv = *(const float4*)(kp + j4 * 4);
                d += kvv.x * sq[head][j4 * 4 + 0] + kvv.y * sq[head][j4 * 4 + 1]
                   + kvv.z * sq[head][j4 * 4 + 2] + kvv.w * sq[head][j4 * 4 + 3];
            }
            logit[s] = d;
        }
    }
    float m = fmaxf(fmaxf(logit[0], logit[1]), logit[2]);
#pragma unroll
    for (int o = 16; o; o >>= 1) m = fmaxf(m, __shfl_xor_sync(~0u, m, o));
    float p[3];
    p[0] = expf(logit[0] - m);
    p[1] = expf(logit[1] - m);
    p[2] = expf(logit[2] - m);
    float ssum = p[0] + p[1] + p[2];
#pragma unroll
    for (int o = 16; o; o >>= 1) ssum += __shfl_xor_sync(~0u, ssum, o);
    float inv = 1.f / ssum;
    float o0 = 0.f, o1 = 0.f;
#pragma unroll
    for (int s = 0; s < 3; s++) {
        int lim = (s == 2) ? 11 : 32;
        for (int src = 0; src < lim; src++) {
            float pa = __shfl_sync(~0u, p[s], src);
            int  np = __shfl_sync(~0u, nn[s], src);
            const float* vp = g_v + hb + (size_t)np * DH_;
            o0 += pa * vp[lane];
            if (lane < 16) o1 += pa * vp[lane + 32];
        }
    }
    float* xp = g_xa + (size_t)n * DIM_ + head * DH_;
    xp[lane] = tf32r(o0 * inv);
    if (lane < 16) xp[lane + 32] = tf32r(o1 * inv);
}

// ---------------- kernel 7: reduce partials + skip + bias + transpose ---------
__global__ void __launch_bounds__(256) k_fin(const float* __restrict__ x,
                                             const float* __restrict__ bm_,
                                             float* __restrict__ out) {
    __shared__ float s[32][33];
    int hw0 = blockIdx.x * 32, c0 = blockIdx.y * 32, t = blockIdx.z;
    int lx = threadIdx.x & 31, lyb = threadIdx.x >> 5;
#pragma unroll
    for (int r = 0; r < 4; r++) {
        int hwl = lyb + r * 8;
        int c = c0 + lx;
        size_t nidx = ((size_t)(t * HW + hw0 + hwl)) * DIM_ + c;
        float sum = bm_[c];
#pragma unroll
        for (int z = 0; z < NSPLIT; z++)
            sum += g_part[(size_t)z * NTOK * DIM_ + nidx];
        s[hwl][lx] = sum;
    }
    __syncthreads();
#pragma unroll
    for (int r = 0; r < 4; r++) {
        int cl = lyb + r * 8;
        size_t oi = ((size_t)(t * DIM_ + c0 + cl)) * HW + hw0 + lx;
        out[oi] = x[oi] + s[lx][cl];
    }
}

// ---------------------------------- launcher ----------------------------------
extern "C" void kernel_launch(void* const* d_in, const int* in_sizes, int n_in,
                              void* d_out, int out_size) {
    const float* x       = (const float*)d_in[0];
    const float* emb     = (const float*)d_in[1];
    const float* w_mod   = (const float*)d_in[2];
    const float* b_mod   = (const float*)d_in[3];
    const float* qn_w    = (const float*)d_in[4];
    const float* qn_b    = (const float*)d_in[5];
    const float* kn_w    = (const float*)d_in[6];
    const float* kn_b    = (const float*)d_in[7];
    const float* W_fused = (const float*)d_in[8];
    const float* b_fused = (const float*)d_in[9];
    const float* W_out   = (const float*)d_in[10];
    const float* W_mlp   = (const float*)d_in[11];
    const float* b_mlp   = (const float*)d_in[12];
    float* out = (float*)d_out;

    static int attr_done = 0;
    if (!attr_done) {
        cudaFuncSetAttribute(k_gemm1_mma, cudaFuncAttributeMaxDynamicSharedMemorySize, SMEM_BYTES);
        cudaFuncSetAttribute(k_gemm2_mma, cudaFuncAttributeMaxDynamicSharedMemorySize, SMEM_BYTES);
        attr_done = 1;
    }

    k_mod<<<dim3(6, 3), 256>>>(emb, w_mod, b_mod);
    k_ln<<<NTOK, 256>>>(x);

    float* wt1 = nullptr; float* wt2 = nullptr;
    cudaGetSymbolAddress((void**)&wt1, g_wt1);
    cudaGetSymbolAddress((void**)&wt2, g_wt2);
    k_tr<<<dim3(FUSED_N / 32, DIM_ / 32), 256>>>(W_fused, wt1, FUSED_N, DIM_, 0);
    k_tr<<<dim3(DIM_ / 32, DIM_ / 32), 256>>>(W_out, wt2, DIM_, K2TOT, 0);
    k_tr<<<dim3(DIM_ / 32, MLP_ / 32), 256>>>(W_mlp, wt2, DIM_, K2TOT, DIM_);

    k_gemm1_mma<<<dim3(FUSED_N / 128, 14), 256, SMEM_BYTES>>>(b_fused);
    k_qkv<<<NTOK, 512>>>(qn_w, qn_b, kn_w, kn_b);
    k_attn<<<NTOK, 512>>>();
    k_gemm2_mma<<<dim3(DIM_ / 128, 14, NSPLIT), 256, SMEM_BYTES>>>();
    k_fin<<<dim3(RESO * RESO / 32, DIM_ / 32, T_), 256>>>(x, b_mlp, out);
}

// round 11
// speedup vs baseline: 3.2536x; 1.2898x over previous
#include <cuda_runtime.h>
#include <math.h>
#include <stdint.h>

#define T_      3
#define RESO    24
#define DIM_    768
#define HEADS_  16
#define DH_     48
#define EMB_    1024
#define MLP_    3072
#define HW      576
#define NTOK    1728
#define FUSED_N 5376
#define QKV_N   2304
#define K2TOT   3840
#define EPS_    1e-5f
#define NSPLIT  6
#define KSPLIT2 640              // K2TOT / NSPLIT
#define MBLKS   112              // ceil(1792/16): padded token m-blocks
#define KB_H    96               // 768/8  k-blocks in h
#define KB_A2   480              // 3840/8 k-blocks in gemm2 A
#define SMEM_BYTES 65536         // 2 bufs x (16KB A + 16KB B)

// ---------------- scratch (device globals, zero-initialized once) --------------
__device__ float g_mod[T_ * 2 * DIM_];
__device__ float g_hP[(size_t)MBLKS * KB_H * 128];      // LN out, fragment-major
__device__ float g_qkv[(size_t)NTOK * QKV_N];           // qkv part of fused, row-major
__device__ float g_aP[(size_t)MBLKS * KB_A2 * 128];     // gemm2 A: [xa | silu(mlp)] fragment-major
__device__ float g_q[HEADS_ * NTOK * DH_];
__device__ float g_k[HEADS_ * NTOK * DH_];
__device__ float g_v[HEADS_ * NTOK * DH_];
__device__ float g_part[(size_t)NSPLIT * NTOK * DIM_];
__device__ float g_wt1P[(size_t)(FUSED_N / 16) * KB_H * 128];   // W_fused^T fragment-major
__device__ float g_wt2P[(size_t)(DIM_ / 16) * KB_A2 * 128];     // [Wo^T|Wm^T] fragment-major

__device__ __forceinline__ float silu_f(float x) { return x / (1.f + expf(-x)); }
__device__ __forceinline__ float tf32r(float x) {
    uint32_t r;
    asm("cvt.rna.tf32.f32 %0, %1;" : "=r"(r) : "f"(x));
    return __uint_as_float(r);
}
__device__ __forceinline__ void cpa16(unsigned dst, const void* src) {
    asm volatile("cp.async.cg.shared.global [%0], [%1], 16;" :: "r"(dst), "l"(src));
}
#define CP_COMMIT() asm volatile("cp.async.commit_group;" ::: "memory")
#define CP_WAIT0()  asm volatile("cp.async.wait_group 0;" ::: "memory")

// fragment-major addressing.
// A atom (16m x 8k): lane = (m&7)*4 + (k&3), j = ((k>>2)&1)*2 + ((m>>3)&1)
__device__ __forceinline__ size_t apos(int m, int k, int KB) {
    return ((size_t)(m >> 4) * KB + (k >> 3)) * 128 +
           (size_t)(((m & 7) * 4 + (k & 3)) * 4 + ((k >> 2) & 1) * 2 + ((m >> 3) & 1));
}
// B pair-atom (16n x 8k): lane = (n&7)*4 + (k&3), j = ((n>>3)&1)*2 + ((k>>2)&1)
__device__ __forceinline__ size_t bpos(int n, int k, int KB) {
    return ((size_t)(n >> 4) * KB + (k >> 3)) * 128 +
           (size_t)(((n & 7) * 4 + (k & 3)) * 4 + ((n >> 3) & 1) * 2 + ((k >> 2) & 1));
}

__device__ __forceinline__ void mma4(float* d, uint4 a, uint32_t b0, uint32_t b1) {
    asm volatile(
        "mma.sync.aligned.m16n8k8.row.col.f32.tf32.tf32.f32 "
        "{%0,%1,%2,%3}, {%4,%5,%6,%7}, {%8,%9}, {%0,%1,%2,%3};"
        : "+f"(d[0]), "+f"(d[1]), "+f"(d[2]), "+f"(d[3])
        : "r"(a.x), "r"(a.y), "r"(a.z), "r"(a.w), "r"(b0), "r"(b1));
}

// copy 32 atoms (8 blocks x 4 k-blocks) = 16KB, pure linear 16B cp.async
__device__ __forceinline__ void load_tile(uint4* smDst, const float* srcBase,
                                          int blk0, int KB, int kblk0, int tid) {
#pragma unroll
    for (int p = 0; p < 4; p++) {
        int lin = p * 256 + tid;
        int atom = lin >> 5, l16 = lin & 31;
        const float* src = srcBase +
            ((size_t)(blk0 + (atom >> 2)) * KB + kblk0 + (atom & 3)) * 128 + l16 * 4;
        cpa16((unsigned)__cvta_generic_to_shared(smDst + atom * 32 + l16), src);
    }
}

// ---------------- kernel: weights -> fragment-major (+tf32 round) --------------
// src [K][N] row-major; dst fragment-major with KB k-blocks, k offset koff.
__global__ void __launch_bounds__(256) k_tr(const float* __restrict__ src,
                                            float* __restrict__ dst,
                                            int N, int KB, int koff) {
    __shared__ float ts[32][33];
    int k0 = blockIdx.y * 32, n0 = blockIdx.x * 32;
    int lx = threadIdx.x & 31, ly = threadIdx.x >> 5;
#pragma unroll
    for (int r = 0; r < 4; r++)
        ts[ly + r * 8][lx] = src[(size_t)(k0 + ly + r * 8) * N + n0 + lx];
    __syncthreads();
    // 8 warps -> 8 atoms (2 npairs x 4 kblks); each warp writes 512B contiguous
    int w = threadIdx.x >> 5, lane = threadIdx.x & 31;
    int npl = w >> 2, kbl = w & 3;
    int g = lane >> 2, tig = lane & 3;
    float4 o;
    float* ov = (float*)&o;
#pragma unroll
    for (int j = 0; j < 4; j++) {
        int n_l = npl * 16 + (j >> 1) * 8 + g;
        int k_l = kbl * 8 + (j & 1) * 4 + tig;
        ov[j] = tf32r(ts[k_l][n_l]);
    }
    size_t atom = ((size_t)((n0 >> 4) + npl) * KB + ((koff + k0) >> 3) + kbl) * 128;
    *(float4*)(dst + atom + lane * 4) = o;
}

// ---------------- kernel 1: mod = silu(emb) @ w_mod + b_mod -------------------
__global__ void k_mod(const float* __restrict__ emb,
                      const float* __restrict__ w_mod,
                      const float* __restrict__ b_mod) {
    __shared__ float se[EMB_];
    int t = blockIdx.y;
    for (int i = threadIdx.x; i < EMB_; i += 256)
        se[i] = silu_f(emb[t * EMB_ + i]);
    __syncthreads();
    int j = blockIdx.x * 256 + threadIdx.x;
    float acc = b_mod[j];
#pragma unroll 4
    for (int e = 0; e < EMB_; e++)
        acc += se[e] * w_mod[e * (2 * DIM_) + j];
    g_mod[t * (2 * DIM_) + j] = acc;
}

// ---------------- kernel 2: h = LN(x)*(1+scale)+shift -> g_hP (fragment-major) -
__global__ void k_ln(const float* __restrict__ x) {
    int n = blockIdx.x;
    int t = n / HW, hw = n % HW;
    const float* xp = x + (size_t)t * DIM_ * HW + hw;
    int c0 = threadIdx.x, c1 = c0 + 256, c2 = c0 + 512;
    float v0 = xp[(size_t)c0 * HW];
    float v1 = xp[(size_t)c1 * HW];
    float v2 = xp[(size_t)c2 * HW];
    float s  = v0 + v1 + v2;
    float sq = v0 * v0 + v1 * v1 + v2 * v2;
    __shared__ float rs[8], rq[8];
#pragma unroll
    for (int o = 16; o; o >>= 1) {
        s  += __shfl_xor_sync(~0u, s, o);
        sq += __shfl_xor_sync(~0u, sq, o);
    }
    int wid = threadIdx.x >> 5, lid = threadIdx.x & 31;
    if (lid == 0) { rs[wid] = s; rq[wid] = sq; }
    __syncthreads();
    if (threadIdx.x == 0) {
        float ts = 0.f, tq = 0.f;
        for (int i = 0; i < 8; i++) { ts += rs[i]; tq += rq[i]; }
        rs[0] = ts; rq[0] = tq;
    }
    __syncthreads();
    float mean = rs[0] * (1.f / DIM_);
    float var  = rq[0] * (1.f / DIM_) - mean * mean;
    float inv  = rsqrtf(var + EPS_);
    const float* md = g_mod + t * (2 * DIM_);
    g_hP[apos(n, c0, KB_H)] = tf32r((v0 - mean) * inv * (1.f + md[c0]) + md[DIM_ + c0]);
    g_hP[apos(n, c1, KB_H)] = tf32r((v1 - mean) * inv * (1.f + md[c1]) + md[DIM_ + c1]);
    g_hP[apos(n, c2, KB_H)] = tf32r((v2 - mean) * inv * (1.f + md[c2]) + md[DIM_ + c2]);
}

// ---------------- GEMM 1: fused = h @ W_fused + b_fused -----------------------
// CTA 128x128, 8 warps (4m x 2n), BK=32, fragment-major smem, all LDS.128.
__global__ void __launch_bounds__(256, 2) k_gemm1_mma(const float* __restrict__ bf) {
    extern __shared__ uint4 smU[];          // [2][A 1024 u4 | B 1024 u4]
    const int tid = threadIdx.x, wid = tid >> 5, lane = tid & 31;
    const int wm = wid & 3, wn = wid >> 2;
    const int g = lane >> 2, tig = lane & 3;
    const int bm = blockIdx.y * 128, BN = blockIdx.x * 128;
    const int mblk0 = bm >> 4, nblk0 = BN >> 4;

    float acc[2][8][4];
#pragma unroll
    for (int a = 0; a < 2; a++)
#pragma unroll
        for (int b = 0; b < 8; b++)
#pragma unroll
            for (int c = 0; c < 4; c++) acc[a][b][c] = 0.f;

    load_tile(smU,        g_hP,   mblk0, KB_H, 0, tid);
    load_tile(smU + 1024, g_wt1P, nblk0, KB_H, 0, tid);
    CP_COMMIT(); CP_WAIT0();
    __syncthreads();

    const int NIT = KB_H / 4;   // 24
    for (int kt = 0; kt < NIT; kt++) {
        int cur = kt & 1, nxt = cur ^ 1;
        if (kt + 1 < NIT) {
            load_tile(smU + nxt * 2048,        g_hP,   mblk0, KB_H, (kt + 1) * 4, tid);
            load_tile(smU + nxt * 2048 + 1024, g_wt1P, nblk0, KB_H, (kt + 1) * 4, tid);
            CP_COMMIT();
        }
        const uint4* Ab = smU + cur * 2048;
        const uint4* Bb = Ab + 1024;
#pragma unroll
        for (int ks = 0; ks < 4; ks++) {
            uint4 a0 = Ab[((wm * 2 + 0) * 4 + ks) * 32 + lane];
            uint4 a1 = Ab[((wm * 2 + 1) * 4 + ks) * 32 + lane];
#pragma unroll
            for (int nbp = 0; nbp < 4; nbp++) {
                uint4 b = Bb[((wn * 4 + nbp) * 4 + ks) * 32 + lane];
                mma4(acc[0][nbp * 2 + 0], a0, b.x, b.y);
                mma4(acc[0][nbp * 2 + 1], a0, b.z, b.w);
                mma4(acc[1][nbp * 2 + 0], a1, b.x, b.y);
                mma4(acc[1][nbp * 2 + 1], a1, b.z, b.w);
            }
        }
        if (kt + 1 < NIT) CP_WAIT0();
        __syncthreads();
    }

    const bool qkv_tile = (BN < QKV_N);
#pragma unroll
    for (int mb = 0; mb < 2; mb++) {
#pragma unroll
        for (int rr = 0; rr < 2; rr++) {
            int row = bm + wm * 32 + mb * 16 + rr * 8 + g;
            if (row >= NTOK) continue;
#pragma unroll
            for (int nb = 0; nb < 8; nb++) {
                int col = BN + wn * 64 + nb * 8 + 2 * tig;
                float vx = acc[mb][nb][rr * 2 + 0] + bf[col];
                float vy = acc[mb][nb][rr * 2 + 1] + bf[col + 1];
                if (qkv_tile) {
                    *(float2*)(g_qkv + (size_t)row * QKV_N + col) = make_float2(vx, vy);
                } else {
                    // mlp part: silu + tf32, scatter into gemm2's fragment-major A
                    g_aP[apos(row, col - 1536, KB_A2)]     = tf32r(silu_f(vx));
                    g_aP[apos(row, col - 1536 + 1, KB_A2)] = tf32r(silu_f(vy));
                }
            }
        }
    }
}

// ---------------- GEMM 2: [xa | silu(mlp)] @ [Wo;Wm], split-K=6 ---------------
__global__ void __launch_bounds__(256, 2) k_gemm2_mma() {
    extern __shared__ uint4 smU[];
    const int tid = threadIdx.x, wid = tid >> 5, lane = tid & 31;
    const int wm = wid & 3, wn = wid >> 2;
    const int g = lane >> 2, tig = lane & 3;
    const int bm = blockIdx.y * 128, BN = blockIdx.x * 128;
    const int z = blockIdx.z;
    const int mblk0 = bm >> 4, nblk0 = BN >> 4;
    const int kblk0 = z * (KSPLIT2 / 8);

    float acc[2][8][4];
#pragma unroll
    for (int a = 0; a < 2; a++)
#pragma unroll
        for (int b = 0; b < 8; b++)
#pragma unroll
            for (int c = 0; c < 4; c++) acc[a][b][c] = 0.f;

    load_tile(smU,        g_aP,   mblk0, KB_A2, kblk0, tid);
    load_tile(smU + 1024, g_wt2P, nblk0, KB_A2, kblk0, tid);
    CP_COMMIT(); CP_WAIT0();
    __syncthreads();

    const int NIT = KSPLIT2 / 32;   // 20
    for (int kt = 0; kt < NIT; kt++) {
        int cur = kt & 1, nxt = cur ^ 1;
        if (kt + 1 < NIT) {
            load_tile(smU + nxt * 2048,        g_aP,   mblk0, KB_A2, kblk0 + (kt + 1) * 4, tid);
            load_tile(smU + nxt * 2048 + 1024, g_wt2P, nblk0, KB_A2, kblk0 + (kt + 1) * 4, tid);
            CP_COMMIT();
        }
        const uint4* Ab = smU + cur * 2048;
        const uint4* Bb = Ab + 1024;
#pragma unroll
        for (int ks = 0; ks < 4; ks++) {
            uint4 a0 = Ab[((wm * 2 + 0) * 4 + ks) * 32 + lane];
            uint4 a1 = Ab[((wm * 2 + 1) * 4 + ks) * 32 + lane];
#pragma unroll
            for (int nbp = 0; nbp < 4; nbp++) {
                uint4 b = Bb[((wn * 4 + nbp) * 4 + ks) * 32 + lane];
                mma4(acc[0][nbp * 2 + 0], a0, b.x, b.y);
                mma4(acc[0][nbp * 2 + 1], a0, b.z, b.w);
                mma4(acc[1][nbp * 2 + 0], a1, b.x, b.y);
                mma4(acc[1][nbp * 2 + 1], a1, b.z, b.w);
            }
        }
        if (kt + 1 < NIT) CP_WAIT0();
        __syncthreads();
    }

#pragma unroll
    for (int mb = 0; mb < 2; mb++) {
#pragma unroll
        for (int rr = 0; rr < 2; rr++) {
            int row = bm + wm * 32 + mb * 16 + rr * 8 + g;
            if (row >= NTOK) continue;
            float* dst = g_part + ((size_t)z * NTOK + row) * DIM_ + BN + wn * 64;
#pragma unroll
            for (int nb = 0; nb < 8; nb++) {
                int col = nb * 8 + 2 * tig;
                *(float2*)(dst + col) =
                    make_float2(acc[mb][nb][rr * 2 + 0], acc[mb][nb][rr * 2 + 1]);
            }
        }
    }
}

// ---------------- kernel 4: qk-norm + RoPE + scatter q/k/v --------------------
__global__ void __launch_bounds__(512) k_qkv(const float* __restrict__ qn_w,
                                             const float* __restrict__ qn_b,
                                             const float* __restrict__ kn_w,
                                             const float* __restrict__ kn_b) {
    int n = blockIdx.x;
    int head = threadIdx.x >> 5;
    int lane = threadIdx.x & 31;
    int t = n / HW, hh = (n % HW) / RESO, ww = n % RESO;
    const float* fp = g_qkv + (size_t)n * QKV_N + head * DH_;
    float2 q2 = make_float2(0.f, 0.f), k2 = q2, v2 = q2;
    if (lane < 24) {
        q2 = *(const float2*)(fp + 2 * lane);
        k2 = *(const float2*)(fp + DIM_ + 2 * lane);
        v2 = *(const float2*)(fp + 2 * DIM_ + 2 * lane);
    }
    float qs = q2.x + q2.y, qq = q2.x * q2.x + q2.y * q2.y;
    float ks = k2.x + k2.y, kq = k2.x * k2.x + k2.y * k2.y;
#pragma unroll
    for (int o = 16; o; o >>= 1) {
        qs += __shfl_xor_sync(~0u, qs, o);
        qq += __shfl_xor_sync(~0u, qq, o);
        ks += __shfl_xor_sync(~0u, ks, o);
        kq += __shfl_xor_sync(~0u, kq, o);
    }
    if (lane < 24) {
        float qm = qs * (1.f / DH_), qv = qq * (1.f / DH_) - qm * qm;
        float km = ks * (1.f / DH_), kv = kq * (1.f / DH_) - km * km;
        float qi = rsqrtf(qv + EPS_), ki = rsqrtf(kv + EPS_);
        int j0 = 2 * lane, j1 = j0 + 1;
        float qn0 = (q2.x - qm) * qi * qn_w[j0] + qn_b[j0];
        float qn1 = (q2.y - qm) * qi * qn_w[j1] + qn_b[j1];
        float kn0 = (k2.x - km) * ki * kn_w[j0] + kn_b[j0];
        float kn1 = (k2.y - km) * ki * kn_w[j1] + kn_b[j1];
        int i = lane;
        int idx;  float pos;
        if (i < 8)       { idx = i;      pos = (float)t;  }
        else if (i < 16) { idx = i - 8;  pos = (float)hh; }
        else             { idx = i - 16; pos = (float)ww; }
        float ang = pos * powf(10000.f, -(float)idx * 0.125f);
        float c = cosf(ang), sn = sinf(ang);
        const float qsc = 0.14433756729740643f;  // 48^-0.5
        size_t base = ((size_t)head * NTOK + n) * DH_;
        *(float2*)(g_q + base + j0) =
            make_float2((qn0 * c - qn1 * sn) * qsc, (qn0 * sn + qn1 * c) * qsc);
        *(float2*)(g_k + base + j0) =
            make_float2(kn0 * c - kn1 * sn, kn0 * sn + kn1 * c);
        *(float2*)(g_v + base + j0) = v2;
    }
}

// ---------------- kernel 5: neighborhood attention (75 nbrs) ------------------
__global__ void __launch_bounds__(512) k_attn() {
    __shared__ float sq[HEADS_][DH_];
    int n = blockIdx.x;
    int head = threadIdx.x >> 5, lane = threadIdx.x & 31;
    int hh = (n % HW) / RESO, ww = n % RESO;
    size_t hb = (size_t)head * NTOK * DH_;
    if (lane < 24)
        *(float2*)&sq[head][2 * lane] = *(const float2*)(g_q + hb + (size_t)n * DH_ + 2 * lane);
    __syncwarp();
    int ih0 = min(max(hh - 2, 0), RESO - 5);
    int iw0 = min(max(ww - 2, 0), RESO - 5);
    float logit[3]; int nn[3];
#pragma unroll
    for (int s = 0; s < 3; s++) {
        int a = s * 32 + lane;
        logit[s] = -1e30f; nn[s] = 0;
        if (a < 75) {
            int at = a / 25, r = a % 25, ah = r / 5, aw = r % 5;
            int np = at * HW + (ih0 + ah) * RESO + (iw0 + aw);
            nn[s] = np;
            const float* kp = g_k + hb + (size_t)np * DH_;
            float d = 0.f;
#pragma unroll
            for (int j4 = 0; j4 < 12; j4++) {
                float4 kvv = *(const float4*)(kp + j4 * 4);
                d += kvv.x * sq[head][j4 * 4 + 0] + kvv.y * sq[head][j4 * 4 + 1]
                   + kvv.z * sq[head][j4 * 4 + 2] + kvv.w * sq[head][j4 * 4 + 3];
            }
            logit[s] = d;
        }
    }
    float m = fmaxf(fmaxf(logit[0], logit[1]), logit[2]);
#pragma unroll
    for (int o = 16; o; o >>= 1) m = fmaxf(m, __shfl_xor_sync(~0u, m, o));
    float p[3];
    p[0] = expf(logit[0] - m);
    p[1] = expf(logit[1] - m);
    p[2] = expf(logit[2] - m);
    float ssum = p[0] + p[1] + p[2];
#pragma unroll
    for (int o = 16; o; o >>= 1) ssum += __shfl_xor_sync(~0u, ssum, o);
    float inv = 1.f / ssum;
    float o0 = 0.f, o1 = 0.f;
#pragma unroll
    for (int s = 0; s < 3; s++) {
        int lim = (s == 2) ? 11 : 32;
        for (int src = 0; src < lim; src++) {
            float pa = __shfl_sync(~0u, p[s], src);
            int  np = __shfl_sync(~0u, nn[s], src);
            const float* vp = g_v + hb + (size_t)np * DH_;
            o0 += pa * vp[lane];
            if (lane < 16) o1 += pa * vp[lane + 32];
        }
    }
    // write xa pre-permuted for gemm2 (k index = channel)
    int ch = head * DH_;
    g_aP[apos(n, ch + lane, KB_A2)] = tf32r(o0 * inv);
    if (lane < 16)
        g_aP[apos(n, ch + 32 + lane, KB_A2)] = tf32r(o1 * inv);
}

// ---------------- kernel 7: reduce partials + skip + bias + transpose ---------
__global__ void __launch_bounds__(256) k_fin(const float* __restrict__ x,
                                             const float* __restrict__ bm_,
                                             float* __restrict__ out) {
    __shared__ float s[32][33];
    int hw0 = blockIdx.x * 32, c0 = blockIdx.y * 32, t = blockIdx.z;
    int lx = threadIdx.x & 31, lyb = threadIdx.x >> 5;
#pragma unroll
    for (int r = 0; r < 4; r++) {
        int hwl = lyb + r * 8;
        int c = c0 + lx;
        size_t nidx = ((size_t)(t * HW + hw0 + hwl)) * DIM_ + c;
        float sum = bm_[c];
#pragma unroll
        for (int z = 0; z < NSPLIT; z++)
            sum += g_part[(size_t)z * NTOK * DIM_ + nidx];
        s[hwl][lx] = sum;
    }
    __syncthreads();
#pragma unroll
    for (int r = 0; r < 4; r++) {
        int cl = lyb + r * 8;
        size_t oi = ((size_t)(t * DIM_ + c0 + cl)) * HW + hw0 + lx;
        out[oi] = x[oi] + s[lx][cl];
    }
}

// ---------------------------------- launcher ----------------------------------
extern "C" void kernel_launch(void* const* d_in, const int* in_sizes, int n_in,
                              void* d_out, int out_size) {
    const float* x       = (const float*)d_in[0];
    const float* emb     = (const float*)d_in[1];
    const float* w_mod   = (const float*)d_in[2];
    const float* b_mod   = (const float*)d_in[3];
    const float* qn_w    = (const float*)d_in[4];
    const float* qn_b    = (const float*)d_in[5];
    const float* kn_w    = (const float*)d_in[6];
    const float* kn_b    = (const float*)d_in[7];
    const float* W_fused = (const float*)d_in[8];
    const float* b_fused = (const float*)d_in[9];
    const float* W_out   = (const float*)d_in[10];
    const float* W_mlp   = (const float*)d_in[11];
    const float* b_mlp   = (const float*)d_in[12];
    float* out = (float*)d_out;

    static int attr_done = 0;
    if (!attr_done) {
        cudaFuncSetAttribute(k_gemm1_mma, cudaFuncAttributeMaxDynamicSharedMemorySize, SMEM_BYTES);
        cudaFuncSetAttribute(k_gemm2_mma, cudaFuncAttributeMaxDynamicSharedMemorySize, SMEM_BYTES);
        attr_done = 1;
    }

    float* wt1 = nullptr; float* wt2 = nullptr;
    cudaGetSymbolAddress((void**)&wt1, g_wt1P);
    cudaGetSymbolAddress((void**)&wt2, g_wt2P);

    k_mod<<<dim3(6, 3), 256>>>(emb, w_mod, b_mod);
    k_ln<<<NTOK, 256>>>(x);
    k_tr<<<dim3(FUSED_N / 32, DIM_ / 32), 256>>>(W_fused, wt1, FUSED_N, KB_H, 0);
    k_tr<<<dim3(DIM_ / 32, DIM_ / 32), 256>>>(W_out, wt2, DIM_, KB_A2, 0);
    k_tr<<<dim3(DIM_ / 32, MLP_ / 32), 256>>>(W_mlp, wt2, DIM_, KB_A2, DIM_);

    k_gemm1_mma<<<dim3(FUSED_N / 128, 14), 256, SMEM_BYTES>>>(b_fused);
    k_qkv<<<NTOK, 512>>>(qn_w, qn_b, kn_w, kn_b);
    k_attn<<<NTOK, 512>>>();
    k_gemm2_mma<<<dim3(DIM_ / 128, 14, NSPLIT), 256, SMEM_BYTES>>>();
    k_fin<<<dim3(RESO * RESO / 32, DIM_ / 32, T_), 256>>>(x, b_mlp, out);
}